// round 14
// baseline (speedup 1.0000x reference)
#include <cuda_runtime.h>
#include <cuda_fp16.h>
#include <math.h>
#include <stdint.h>

#define BATCH 4096
#define NVAR  16
#define DDIM  256
#define FEAT  4096
#define NELEM ((size_t)BATCH * FEAT)     // 16,777,216
#define VWN   ((size_t)NVAR * DDIM * DDIM)

// ---------------- scratch (device globals; allocation forbidden) -----------
__device__ __align__(256) float g_buf0[NELEM];   // concat GLU result g
__device__ __align__(256) float g_buf2[NELEM];   // var GLU result gv
// fp16 activations
__device__ __align__(256) __half g_xh[NELEM];
__device__ __align__(256) __half g_hh[NELEM];    // concat h, then t4 (fp16)
__device__ __align__(256) __half g_eh[NELEM];    // concat e1
__device__ __align__(256) __half g_hv[NELEM];    // var h, then t4v (fp16)
__device__ __align__(256) __half g_ev[NELEM];    // var e1
// transposed fp16 weights
__device__ __align__(256) __half g_cW2h[NELEM];
__device__ __align__(256) __half g_cW1h[NELEM];
__device__ __align__(256) __half g_cW4h[NELEM];
__device__ __align__(256) __half g_cW5h[NELEM];
__device__ __align__(256) __half g_vW2h[VWN];
__device__ __align__(256) __half g_vW1h[VWN];
__device__ __align__(256) __half g_vW4h[VWN];
__device__ __align__(256) __half g_vW5h[VWN];

// ---------------- helpers ---------------------------------------------------
__device__ __forceinline__ uint32_t smem_u32(const void* p) {
    uint32_t a;
    asm("{ .reg .u64 t; cvta.to.shared.u64 t, %1; cvt.u32.u64 %0, t; }"
        : "=r"(a) : "l"(p));
    return a;
}

#define CP_ASYNC16(dst, src) \
    asm volatile("cp.async.cg.shared.global [%0], [%1], 16;" :: "r"(dst), "l"(src))
#define CP_COMMIT() asm volatile("cp.async.commit_group;" ::: "memory")
#define CP_WAIT3()  asm volatile("cp.async.wait_group 3;" ::: "memory")

#define LDSM4(r, a) \
    asm volatile("ldmatrix.sync.aligned.m8n8.x4.shared.b16 {%0,%1,%2,%3}, [%4];" \
                 : "=r"((r)[0]), "=r"((r)[1]), "=r"((r)[2]), "=r"((r)[3]) : "r"(a))

// fp16-accumulate MMA, C = 0: D(f16x2 x2) = A*B (K=16 internal exact sum).
__device__ __forceinline__ void mma16816_h(uint32_t* d, const uint32_t* a,
                                           uint32_t b0, uint32_t b1) {
    asm volatile(
        "mma.sync.aligned.m16n8k16.row.col.f16.f16.f16.f16 "
        "{%0,%1}, {%2,%3,%4,%5}, {%6,%7}, {%8,%9};"
        : "=r"(d[0]), "=r"(d[1])
        : "r"(a[0]), "r"(a[1]), "r"(a[2]), "r"(a[3]), "r"(b0), "r"(b1),
          "r"(0u), "r"(0u));
}

// flush f16 D pair into fp32 master accumulators
__device__ __forceinline__ void addf(float* a, const uint32_t* d) {
    float2 lo = __half22float2(*reinterpret_cast<const __half2*>(&d[0]));
    float2 hi = __half22float2(*reinterpret_cast<const __half2*>(&d[1]));
    a[0] += lo.x; a[1] += lo.y; a[2] += hi.x; a[3] += hi.y;
}

// ---------------- merged GEMM (mma.sync f16-D) — R13 schedule --------------
// BM=BN=128, BK=32, 256 threads (8 warps: 2m x 4n), warp tile 64x32.
// 2 CTAs/SM (16 warps/SM).
#define BM 128
#define BN 128
#define BK 32
#define ROWB 80
#define A_BYTES (BM * ROWB)              // 10240
#define B_BYTES (BN * ROWB)              // 10240
#define STAGEB (A_BYTES + B_BYTES)       // 20480
#define NSTAGE 5
#define GEMM_SMEM (NSTAGE * STAGEB)      // 102400

struct GDesc {
    const __half* A;
    const __half* B;
    const float*  bias;
    const __half* AuxH;      // fp16 aux (GLU gate input t4)
    float*        Cf;
    __half*       Ch;
    int  K, lda, ldb, ldc;
    long sAn, sBn, sBiasN, sCn;
    int  ntN, tilesPerZ;
};

__device__ __forceinline__ void load_chunk(
    uint32_t s0, int tid, int k0,
    const __half* __restrict__ Ah, int lda, int bm,
    const __half* __restrict__ Bh, int ldb, int bn)
{
#pragma unroll
    for (int r = 0; r < 2; r++) {        // A: 128 rows x 4 segs
        int e = tid + r * 256;
        int row = e >> 2, seg = e & 3;
        CP_ASYNC16(s0 + (uint32_t)row * ROWB + seg * 16,
                   Ah + (size_t)(bm + row) * lda + k0 + seg * 8);
    }
#pragma unroll
    for (int r = 0; r < 2; r++) {        // B: 128 rows x 4 segs
        int e = tid + r * 256;
        int row = e >> 2, seg = e & 3;
        CP_ASYNC16(s0 + A_BYTES + (uint32_t)row * ROWB + seg * 16,
                   Bh + (size_t)(bn + row) * ldb + k0 + seg * 8);
    }
}

// ACT: 0 none, 1 ELU, 2 GLU (v *= sigmoid(auxH)). OUT16: 1 fp16, 0 fp32.
template <int ACT, int OUT16>
__global__ __launch_bounds__(256, 2)
void mgemm_k(GDesc c0, GDesc c1, int tiles0)
{
    extern __shared__ char smem[];
    const uint32_t sbase = smem_u32(smem);
    const int tid = threadIdx.x;
    const int bx = blockIdx.x;

    GDesc d;
    int nb, tm, tn;
    if (bx < tiles0) {
        d = c0; nb = 0;
        tm = bx / d.ntN; tn = bx % d.ntN;
    } else {
        d = c1;
        int v = bx - tiles0;
        nb = v / d.tilesPerZ;
        int rem = v % d.tilesPerZ;
        tm = rem / d.ntN; tn = rem % d.ntN;
    }
    const __half* Ah = d.A + (size_t)nb * d.sAn;
    const __half* Bh = d.B + (size_t)nb * d.sBn;
    const float* bias = d.bias + (size_t)nb * d.sBiasN;
    const size_t coff = (size_t)nb * d.sCn;
    const int lda = d.lda, ldb = d.ldb, ldc = d.ldc, K = d.K;
    const int bm = tm * BM, bn = tn * BN;

    const int lane = tid & 31, wid = tid >> 5;
    const int wm = wid & 1, wn = wid >> 1;       // 2(m) x 4(n)
    const int lr = lane & 15, lc = lane >> 4;

    float acc[4][4][4];                           // warp tile 64x32 fp32 master
#pragma unroll
    for (int a = 0; a < 4; a++)
#pragma unroll
        for (int b = 0; b < 4; b++)
#pragma unroll
            for (int c = 0; c < 4; c++) acc[a][b][c] = 0.f;

    const int nk = K / BK;
#pragma unroll
    for (int j = 0; j < 4; j++) {
        if (j < nk)
            load_chunk(sbase + j * STAGEB, tid, j * BK, Ah, lda, bm, Bh, ldb, bn);
        CP_COMMIT();
    }

    int stR = 0, stW = 4;
    for (int i = 0; i < nk; i++) {
        CP_WAIT3();
        __syncthreads();
        const uint32_t sb = sbase + (uint32_t)stR * STAGEB;
        const uint32_t raBase = sb + (uint32_t)(wm * 64 + lr) * ROWB;
        const uint32_t rbBase = sb + A_BYTES + (uint32_t)(wn * 32 + lr) * ROWB;

#pragma unroll
        for (int ks = 0; ks < 2; ks++) {
            const uint32_t koff = (uint32_t)(ks * 16 + lc * 8) * 2;
            uint32_t ah[4][4];
#pragma unroll
            for (int mt = 0; mt < 4; mt++)
                LDSM4(ah[mt], raBase + (uint32_t)(mt * 16) * ROWB + koff);
#pragma unroll
            for (int nt = 0; nt < 2; nt++) {
                uint32_t bh[4];
                LDSM4(bh, rbBase + (uint32_t)(nt * 16) * ROWB + koff);
#pragma unroll
                for (int mt = 0; mt < 4; mt++) {
                    uint32_t dz[2];
                    mma16816_h(dz, ah[mt], bh[0], bh[2]);
                    addf(acc[mt][nt * 2 + 0], dz);
                    mma16816_h(dz, ah[mt], bh[1], bh[3]);
                    addf(acc[mt][nt * 2 + 1], dz);
                }
            }
        }

        int j = i + 4;
        if (j < nk)
            load_chunk(sbase + (uint32_t)stW * STAGEB, tid, j * BK,
                       Ah, lda, bm, Bh, ldb, bn);
        CP_COMMIT();
        stR = (stR + 1 == NSTAGE) ? 0 : stR + 1;
        stW = (stW + 1 == NSTAGE) ? 0 : stW + 1;
    }

    // Epilogue: warp tile 64x32.
    const int rbase = bm + wm * 64 + (lane >> 2);
    const int cbase = bn + wn * 32 + (lane & 3) * 2;
#pragma unroll
    for (int mt = 0; mt < 4; mt++) {
#pragma unroll
        for (int t8 = 0; t8 < 4; t8++) {
            const int r = rbase + mt * 16;
            const int c = cbase + t8 * 8;
            const float b0 = bias[c], b1 = bias[c + 1];
            float v00 = acc[mt][t8][0] + b0, v01 = acc[mt][t8][1] + b1;
            float v10 = acc[mt][t8][2] + b0, v11 = acc[mt][t8][3] + b1;
            if (ACT == 1) {
                v00 = v00 > 0.f ? v00 : expm1f(v00);
                v01 = v01 > 0.f ? v01 : expm1f(v01);
                v10 = v10 > 0.f ? v10 : expm1f(v10);
                v11 = v11 > 0.f ? v11 : expm1f(v11);
            }
            if (ACT == 2) {
                __half2 a0 = *(const __half2*)(d.AuxH + coff + (size_t)r * ldc + c);
                __half2 a1 = *(const __half2*)(d.AuxH + coff + (size_t)(r + 8) * ldc + c);
                float2 f0 = __half22float2(a0);
                float2 f1 = __half22float2(a1);
                v00 *= 1.f / (1.f + expf(-f0.x));
                v01 *= 1.f / (1.f + expf(-f0.y));
                v10 *= 1.f / (1.f + expf(-f1.x));
                v11 *= 1.f / (1.f + expf(-f1.y));
            }
            if (OUT16) {
                __half2 H0 = __floats2half2_rn(v00, v01);
                __half2 H1 = __floats2half2_rn(v10, v11);
                *(uint32_t*)(d.Ch + coff + (size_t)r * ldc + c) =
                    *reinterpret_cast<uint32_t*>(&H0);
                *(uint32_t*)(d.Ch + coff + (size_t)(r + 8) * ldc + c) =
                    *reinterpret_cast<uint32_t*>(&H1);
            } else {
                *(float2*)(d.Cf + coff + (size_t)r * ldc + c) = make_float2(v00, v01);
                *(float2*)(d.Cf + coff + (size_t)(r + 8) * ldc + c) = make_float2(v10, v11);
            }
        }
    }
}

// ---------------- convert fp32 -> fp16 -------------------------------------
__global__ __launch_bounds__(256)
void cvt16_k(const float* __restrict__ src, __half* __restrict__ dst, size_t n)
{
    size_t i = ((size_t)blockIdx.x * blockDim.x + threadIdx.x) * 4;
    if (i >= n) return;
    float4 v = *(const float4*)(src + i);
    __half2 h0 = __floats2half2_rn(v.x, v.y);
    __half2 h1 = __floats2half2_rn(v.z, v.w);
    uint2 o = { *reinterpret_cast<uint32_t*>(&h0), *reinterpret_cast<uint32_t*>(&h1) };
    *(uint2*)((unsigned short*)dst + i) = o;
}

// ---------------- transpose + convert, 4 weights per launch ----------------
__global__ __launch_bounds__(256)
void tcvt4_k(const float* __restrict__ s0, const float* __restrict__ s1,
             const float* __restrict__ s2, const float* __restrict__ s3,
             __half* __restrict__ d0, __half* __restrict__ d1,
             __half* __restrict__ d2, __half* __restrict__ d3,
             int K, int Ncol, int zPerW)
{
    __shared__ float t[64][33];
    int w = blockIdx.z / zPerW;
    int z = blockIdx.z % zPerW;
    const float* src = (w == 0 ? s0 : w == 1 ? s1 : w == 2 ? s2 : s3)
                       + (size_t)z * K * Ncol;
    __half* dst = (w == 0 ? d0 : w == 1 ? d1 : w == 2 ? d2 : d3)
                  + (size_t)z * K * Ncol;
    int k0 = blockIdx.y * 64, n0 = blockIdx.x * 32;
#pragma unroll
    for (int r = 0; r < 8; r++)
        t[threadIdx.y + 8 * r][threadIdx.x] =
            src[(size_t)(k0 + threadIdx.y + 8 * r) * Ncol + n0 + threadIdx.x];
    __syncthreads();
#pragma unroll
    for (int r = 0; r < 4; r++) {
        int n = threadIdx.y + 8 * r;
        int kk = threadIdx.x;
        __half2 h = __floats2half2_rn(t[2 * kk][n], t[2 * kk + 1][n]);
        *(__half2*)(dst + (size_t)(n0 + n) * K + k0 + 2 * kk) = h;
    }
}

// ---------------- fused LN(4096)+softmax + per-(b,n) LN(256)+combine -------
__global__ __launch_bounds__(256)
void final_k(const float* __restrict__ x, const float* __restrict__ g,
             const float* __restrict__ gamma, const float* __restrict__ beta,
             const float* __restrict__ gv, const float* __restrict__ vlng,
             const float* __restrict__ vlnb, float* __restrict__ out)
{
    __shared__ float s[FEAT];
    __shared__ float red[8];
    __shared__ float part[8][DDIM];
    const int b = blockIdx.x, t = threadIdx.x;
    const int lane = t & 31, wrp = t >> 5;
    const float* xb = x + (size_t)b * FEAT;
    const float* gb = g + (size_t)b * FEAT;

    float lsum = 0.f;
    for (int i = t; i < FEAT; i += 256) {
        float v = xb[i] + gb[i];
        s[i] = v; lsum += v;
    }
#pragma unroll
    for (int o = 16; o; o >>= 1) lsum += __shfl_xor_sync(0xffffffff, lsum, o);
    if (lane == 0) red[wrp] = lsum;
    __syncthreads();
    float tot = 0.f;
#pragma unroll
    for (int i = 0; i < 8; i++) tot += red[i];
    float mean = tot * (1.f / FEAT);
    __syncthreads();

    float lvar = 0.f;
    for (int i = t; i < FEAT; i += 256) { float dd = s[i] - mean; lvar += dd * dd; }
#pragma unroll
    for (int o = 16; o; o >>= 1) lvar += __shfl_xor_sync(0xffffffff, lvar, o);
    if (lane == 0) red[wrp] = lvar;
    __syncthreads();
    float vtot = 0.f;
#pragma unroll
    for (int i = 0; i < 8; i++) vtot += red[i];
    float rstd = rsqrtf(vtot * (1.f / FEAT) + 1e-5f);

    for (int i = t; i < FEAT; i += 256)
        s[i] = (s[i] - mean) * rstd * gamma[i] + beta[i];
    __syncthreads();

    {
        float c[NVAR];
        float m = -1e30f;
#pragma unroll
        for (int n = 0; n < NVAR; n++) { c[n] = s[n * DDIM + t]; m = fmaxf(m, c[n]); }
        float sum = 0.f;
#pragma unroll
        for (int n = 0; n < NVAR; n++) { c[n] = expf(c[n] - m); sum += c[n]; }
        float inv = 1.f / sum;
#pragma unroll
        for (int n = 0; n < NVAR; n++) s[n * DDIM + t] = c[n] * inv;
    }
    __syncthreads();

    float accl[8];
#pragma unroll
    for (int j = 0; j < 8; j++) accl[j] = 0.f;

#pragma unroll
    for (int nn = 0; nn < 2; nn++) {
        const int n = wrp * 2 + nn;
        const size_t base = (size_t)b * FEAT + n * DDIM;
        float v[8];
        float sum = 0.f;
#pragma unroll
        for (int j = 0; j < 8; j++) {
            v[j] = x[base + lane + 32 * j] + gv[base + lane + 32 * j];
            sum += v[j];
        }
#pragma unroll
        for (int o = 16; o; o >>= 1) sum += __shfl_xor_sync(0xffffffff, sum, o);
        const float meanl = sum * (1.f / DDIM);
        float var = 0.f;
#pragma unroll
        for (int j = 0; j < 8; j++) { float dl = v[j] - meanl; var += dl * dl; }
#pragma unroll
        for (int o = 16; o; o >>= 1) var += __shfl_xor_sync(0xffffffff, var, o);
        const float rstdl = rsqrtf(var * (1.f / DDIM) + 1e-5f);
#pragma unroll
        for (int j = 0; j < 8; j++) {
            const int dcol = lane + 32 * j;
            float yv = (v[j] - meanl) * rstdl * vlng[n * DDIM + dcol]
                       + vlnb[n * DDIM + dcol];
            accl[j] += s[n * DDIM + dcol] * yv;
        }
    }
#pragma unroll
    for (int j = 0; j < 8; j++) part[wrp][lane + 32 * j] = accl[j];
    __syncthreads();
    float sm = 0.f;
#pragma unroll
    for (int k = 0; k < 8; k++) sm += part[k][t];
    out[(size_t)b * DDIM + t] = sm;
}

// ---------------- launch ----------------------------------------------------
extern "C" void kernel_launch(void* const* d_in, const int* in_sizes, int n_in,
                              void* d_out, int out_size)
{
    const float* x    = (const float*)d_in[0];
    const float* vW2  = (const float*)d_in[1];
    const float* vb2  = (const float*)d_in[2];
    const float* vW1  = (const float*)d_in[3];
    const float* vb1  = (const float*)d_in[4];
    const float* vW4  = (const float*)d_in[5];
    const float* vb4  = (const float*)d_in[6];
    const float* vW5  = (const float*)d_in[7];
    const float* vb5  = (const float*)d_in[8];
    const float* vlng = (const float*)d_in[9];
    const float* vlnb = (const float*)d_in[10];
    const float* cW2  = (const float*)d_in[11];
    const float* cb2  = (const float*)d_in[12];
    const float* cW1  = (const float*)d_in[13];
    const float* cb1  = (const float*)d_in[14];
    const float* cW4  = (const float*)d_in[15];
    const float* cb4  = (const float*)d_in[16];
    const float* cW5  = (const float*)d_in[17];
    const float* cb5  = (const float*)d_in[18];
    const float* clng = (const float*)d_in[19];
    const float* clnb = (const float*)d_in[20];
    float* out = (float*)d_out;

    float *buf0, *buf2;
    cudaGetSymbolAddress((void**)&buf0, g_buf0);
    cudaGetSymbolAddress((void**)&buf2, g_buf2);
    __half *xh, *hh, *eh, *hv, *ev;
    cudaGetSymbolAddress((void**)&xh, g_xh);
    cudaGetSymbolAddress((void**)&hh, g_hh);
    cudaGetSymbolAddress((void**)&eh, g_eh);
    cudaGetSymbolAddress((void**)&hv, g_hv);
    cudaGetSymbolAddress((void**)&ev, g_ev);
    __half *cW2h, *cW1h, *cW4h, *cW5h;
    cudaGetSymbolAddress((void**)&cW2h, g_cW2h);
    cudaGetSymbolAddress((void**)&cW1h, g_cW1h);
    cudaGetSymbolAddress((void**)&cW4h, g_cW4h);
    cudaGetSymbolAddress((void**)&cW5h, g_cW5h);
    __half *vW2h, *vW1h, *vW4h, *vW5h;
    cudaGetSymbolAddress((void**)&vW2h, g_vW2h);
    cudaGetSymbolAddress((void**)&vW1h, g_vW1h);
    cudaGetSymbolAddress((void**)&vW4h, g_vW4h);
    cudaGetSymbolAddress((void**)&vW5h, g_vW5h);

    cudaFuncSetAttribute(mgemm_k<1, 1>, cudaFuncAttributeMaxDynamicSharedMemorySize, GEMM_SMEM);
    cudaFuncSetAttribute(mgemm_k<0, 1>, cudaFuncAttributeMaxDynamicSharedMemorySize, GEMM_SMEM);
    cudaFuncSetAttribute(mgemm_k<2, 0>, cudaFuncAttributeMaxDynamicSharedMemorySize, GEMM_SMEM);

    const size_t NE = NELEM;

    // ---- conversions ----
    cvt16_k<<<(unsigned)(NE / 1024), 256>>>(x, xh, NE);
    {
        dim3 b(32, 8);
        dim3 gc(FEAT / 32, FEAT / 64, 4);
        tcvt4_k<<<gc, b>>>(cW2, cW1, cW4, cW5, cW2h, cW1h, cW4h, cW5h,
                           FEAT, FEAT, 1);
        dim3 gv(DDIM / 32, DDIM / 64, 4 * NVAR);
        tcvt4_k<<<gv, b>>>(vW2, vW1, vW4, vW5, vW2h, vW1h, vW4h, vW5h,
                           DDIM, DDIM, NVAR);
    }

    // ---- descriptor templates ----
    const int ccTiles = (FEAT / BN) * (BATCH / BM);   // 32*32 = 1024
    const int vTilesZ = (DDIM / BN) * (BATCH / BM);   // 2*32  = 64
    const int vTiles  = vTilesZ * NVAR;               // 1024
    const unsigned totalTiles = ccTiles + vTiles;     // 2048

    auto mkC = [&](const __half* A, const __half* B, const float* bias,
                   const __half* auxh, float* cf, __half* ch) {
        GDesc d;
        d.A = A; d.B = B; d.bias = bias; d.AuxH = auxh; d.Cf = cf; d.Ch = ch;
        d.K = FEAT; d.lda = FEAT; d.ldb = FEAT; d.ldc = FEAT;
        d.sAn = 0; d.sBn = 0; d.sBiasN = 0; d.sCn = 0;
        d.ntN = FEAT / BN; d.tilesPerZ = ccTiles;
        return d;
    };
    auto mkV = [&](const __half* A, const __half* B, const float* bias,
                   const __half* auxh, float* cf, __half* ch) {
        GDesc d;
        d.A = A; d.B = B; d.bias = bias; d.AuxH = auxh; d.Cf = cf; d.Ch = ch;
        d.K = DDIM; d.lda = FEAT; d.ldb = DDIM; d.ldc = FEAT;
        d.sAn = DDIM; d.sBn = (long)DDIM * DDIM; d.sBiasN = DDIM; d.sCn = DDIM;
        d.ntN = DDIM / BN; d.tilesPerZ = vTilesZ;
        return d;
    };

    // ---- merged GEMM launches ----
    // L1: h = elu(x@W2+b2)  -> hh / hv (fp16)
    mgemm_k<1, 1><<<totalTiles, 256, GEMM_SMEM>>>(
        mkC(xh, cW2h, cb2, nullptr, nullptr, hh),
        mkV(xh, vW2h, vb2, nullptr, nullptr, hv), ccTiles);
    // L2: e1 = h@W1+b1      -> eh / ev (fp16)
    mgemm_k<0, 1><<<totalTiles, 256, GEMM_SMEM>>>(
        mkC(hh, cW1h, cb1, nullptr, nullptr, eh),
        mkV(hv, vW1h, vb1, nullptr, nullptr, ev), ccTiles);
    // L3: t4 = e1@W4+b4     -> hh / hv (fp16)
    mgemm_k<0, 1><<<totalTiles, 256, GEMM_SMEM>>>(
        mkC(eh, cW4h, cb4, nullptr, nullptr, hh),
        mkV(ev, vW4h, vb4, nullptr, nullptr, hv), ccTiles);
    // L4: g = sigmoid(t4) * (e1@W5+b5)  -> buf0 / buf2 (fp32)
    mgemm_k<2, 0><<<totalTiles, 256, GEMM_SMEM>>>(
        mkC(eh, cW5h, cb5, hh, buf0, nullptr),
        mkV(ev, vW5h, vb5, hv, buf2, nullptr), ccTiles);

    // ---- fused LN+softmax+combine ----
    final_k<<<BATCH, 256>>>(x, buf0, clng, clnb, buf2, vlng, vlnb, out);
}

// round 15
// speedup vs baseline: 1.3617x; 1.3617x over previous
#include <cuda_runtime.h>
#include <cuda_fp16.h>
#include <math.h>
#include <stdint.h>

#define BATCH 4096
#define NVAR  16
#define DDIM  256
#define FEAT  4096
#define NELEM ((size_t)BATCH * FEAT)     // 16,777,216
#define VWN   ((size_t)NVAR * DDIM * DDIM)

// ---------------- scratch (device globals; allocation forbidden) -----------
__device__ __align__(256) __half g_gc[NELEM];    // concat GLU result g (fp16)
__device__ __align__(256) __half g_gv[NELEM];    // var GLU result gv (fp16)
// fp16 activations
__device__ __align__(256) __half g_xh[NELEM];
__device__ __align__(256) __half g_hh[NELEM];    // concat h, then t4 (fp16)
__device__ __align__(256) __half g_eh[NELEM];    // concat e1
__device__ __align__(256) __half g_hv[NELEM];    // var h, then t4v (fp16)
__device__ __align__(256) __half g_ev[NELEM];    // var e1
// transposed fp16 weights
__device__ __align__(256) __half g_cW2h[NELEM];
__device__ __align__(256) __half g_cW1h[NELEM];
__device__ __align__(256) __half g_cW4h[NELEM];
__device__ __align__(256) __half g_cW5h[NELEM];
__device__ __align__(256) __half g_vW2h[VWN];
__device__ __align__(256) __half g_vW1h[VWN];
__device__ __align__(256) __half g_vW4h[VWN];
__device__ __align__(256) __half g_vW5h[VWN];

// ---------------- helpers ---------------------------------------------------
__device__ __forceinline__ uint32_t smem_u32(const void* p) {
    uint32_t a;
    asm("{ .reg .u64 t; cvta.to.shared.u64 t, %1; cvt.u32.u64 %0, t; }"
        : "=r"(a) : "l"(p));
    return a;
}

#define CP_ASYNC16(dst, src) \
    asm volatile("cp.async.cg.shared.global [%0], [%1], 16;" :: "r"(dst), "l"(src))
#define CP_COMMIT() asm volatile("cp.async.commit_group;" ::: "memory")
#define CP_WAIT3()  asm volatile("cp.async.wait_group 3;" ::: "memory")

#define LDSM4(r, a) \
    asm volatile("ldmatrix.sync.aligned.m8n8.x4.shared.b16 {%0,%1,%2,%3}, [%4];" \
                 : "=r"((r)[0]), "=r"((r)[1]), "=r"((r)[2]), "=r"((r)[3]) : "r"(a))

__device__ __forceinline__ void mma16816(float* d, const uint32_t* a,
                                         uint32_t b0, uint32_t b1) {
    asm volatile(
        "mma.sync.aligned.m16n8k16.row.col.f32.f16.f16.f32 "
        "{%0,%1,%2,%3}, {%4,%5,%6,%7}, {%8,%9}, {%0,%1,%2,%3};"
        : "+f"(d[0]), "+f"(d[1]), "+f"(d[2]), "+f"(d[3])
        : "r"(a[0]), "r"(a[1]), "r"(a[2]), "r"(a[3]), "r"(b0), "r"(b1));
}

// ---------------- merged GEMM (mma.sync fp16) — R13 schedule ---------------
// BM=BN=128, BK=32, 256 threads (8 warps: 2m x 4n), warp tile 64x32.
// 2 CTAs/SM (16 warps/SM).
#define BM 128
#define BN 128
#define BK 32
#define ROWB 80
#define A_BYTES (BM * ROWB)              // 10240
#define B_BYTES (BN * ROWB)              // 10240
#define STAGEB (A_BYTES + B_BYTES)       // 20480
#define NSTAGE 5
#define GEMM_SMEM (NSTAGE * STAGEB)      // 102400

struct GDesc {
    const __half* A;
    const __half* B;
    const float*  bias;
    const __half* AuxH;      // fp16 aux (GLU gate input t4)
    __half*       Ch;        // fp16 output
    int  K, lda, ldb, ldc;
    long sAn, sBn, sBiasN, sCn;
    int  ntN, tilesPerZ;
};

__device__ __forceinline__ void load_chunk(
    uint32_t s0, int tid, int k0,
    const __half* __restrict__ Ah, int lda, int bm,
    const __half* __restrict__ Bh, int ldb, int bn)
{
#pragma unroll
    for (int r = 0; r < 2; r++) {        // A: 128 rows x 4 segs
        int e = tid + r * 256;
        int row = e >> 2, seg = e & 3;
        CP_ASYNC16(s0 + (uint32_t)row * ROWB + seg * 16,
                   Ah + (size_t)(bm + row) * lda + k0 + seg * 8);
    }
#pragma unroll
    for (int r = 0; r < 2; r++) {        // B: 128 rows x 4 segs
        int e = tid + r * 256;
        int row = e >> 2, seg = e & 3;
        CP_ASYNC16(s0 + A_BYTES + (uint32_t)row * ROWB + seg * 16,
                   Bh + (size_t)(bn + row) * ldb + k0 + seg * 8);
    }
}

// ACT: 0 none, 1 ELU, 2 GLU (v *= sigmoid(auxH)). Output always fp16.
template <int ACT>
__global__ __launch_bounds__(256, 2)
void mgemm_k(GDesc c0, GDesc c1, int tiles0)
{
    extern __shared__ char smem[];
    const uint32_t sbase = smem_u32(smem);
    const int tid = threadIdx.x;
    const int bx = blockIdx.x;

    GDesc d;
    int nb, tm, tn;
    if (bx < tiles0) {
        d = c0; nb = 0;
        tm = bx / d.ntN; tn = bx % d.ntN;
    } else {
        d = c1;
        int v = bx - tiles0;
        nb = v / d.tilesPerZ;
        int rem = v % d.tilesPerZ;
        tm = rem / d.ntN; tn = rem % d.ntN;
    }
    const __half* Ah = d.A + (size_t)nb * d.sAn;
    const __half* Bh = d.B + (size_t)nb * d.sBn;
    const float* bias = d.bias + (size_t)nb * d.sBiasN;
    const size_t coff = (size_t)nb * d.sCn;
    const int lda = d.lda, ldb = d.ldb, ldc = d.ldc, K = d.K;
    const int bm = tm * BM, bn = tn * BN;

    const int lane = tid & 31, wid = tid >> 5;
    const int wm = wid & 1, wn = wid >> 1;       // 2(m) x 4(n)
    const int lr = lane & 15, lc = lane >> 4;

    float acc[4][4][4];                           // warp tile 64x32
#pragma unroll
    for (int a = 0; a < 4; a++)
#pragma unroll
        for (int b = 0; b < 4; b++)
#pragma unroll
            for (int c = 0; c < 4; c++) acc[a][b][c] = 0.f;

    const int nk = K / BK;
#pragma unroll
    for (int j = 0; j < 4; j++) {
        if (j < nk)
            load_chunk(sbase + j * STAGEB, tid, j * BK, Ah, lda, bm, Bh, ldb, bn);
        CP_COMMIT();
    }

    int stR = 0, stW = 4;
    for (int i = 0; i < nk; i++) {
        CP_WAIT3();
        __syncthreads();
        const uint32_t sb = sbase + (uint32_t)stR * STAGEB;
        const uint32_t raBase = sb + (uint32_t)(wm * 64 + lr) * ROWB;
        const uint32_t rbBase = sb + A_BYTES + (uint32_t)(wn * 32 + lr) * ROWB;

#pragma unroll
        for (int ks = 0; ks < 2; ks++) {
            const uint32_t koff = (uint32_t)(ks * 16 + lc * 8) * 2;
            uint32_t ah[4][4];
#pragma unroll
            for (int mt = 0; mt < 4; mt++)
                LDSM4(ah[mt], raBase + (uint32_t)(mt * 16) * ROWB + koff);
#pragma unroll
            for (int nt = 0; nt < 2; nt++) {
                uint32_t bh[4];
                LDSM4(bh, rbBase + (uint32_t)(nt * 16) * ROWB + koff);
#pragma unroll
                for (int mt = 0; mt < 4; mt++) {
                    mma16816(acc[mt][nt * 2 + 0], ah[mt], bh[0], bh[2]);
                    mma16816(acc[mt][nt * 2 + 1], ah[mt], bh[1], bh[3]);
                }
            }
        }

        int j = i + 4;
        if (j < nk)
            load_chunk(sbase + (uint32_t)stW * STAGEB, tid, j * BK,
                       Ah, lda, bm, Bh, ldb, bn);
        CP_COMMIT();
        stR = (stR + 1 == NSTAGE) ? 0 : stR + 1;
        stW = (stW + 1 == NSTAGE) ? 0 : stW + 1;
    }

    // Epilogue: warp tile 64x32; fp16 output.
    const int rbase = bm + wm * 64 + (lane >> 2);
    const int cbase = bn + wn * 32 + (lane & 3) * 2;
#pragma unroll
    for (int mt = 0; mt < 4; mt++) {
#pragma unroll
        for (int t8 = 0; t8 < 4; t8++) {
            const int r = rbase + mt * 16;
            const int c = cbase + t8 * 8;
            const float b0 = bias[c], b1 = bias[c + 1];
            float v00 = acc[mt][t8][0] + b0, v01 = acc[mt][t8][1] + b1;
            float v10 = acc[mt][t8][2] + b0, v11 = acc[mt][t8][3] + b1;
            if (ACT == 1) {
                v00 = v00 > 0.f ? v00 : expm1f(v00);
                v01 = v01 > 0.f ? v01 : expm1f(v01);
                v10 = v10 > 0.f ? v10 : expm1f(v10);
                v11 = v11 > 0.f ? v11 : expm1f(v11);
            }
            if (ACT == 2) {
                __half2 a0 = *(const __half2*)(d.AuxH + coff + (size_t)r * ldc + c);
                __half2 a1 = *(const __half2*)(d.AuxH + coff + (size_t)(r + 8) * ldc + c);
                float2 f0 = __half22float2(a0);
                float2 f1 = __half22float2(a1);
                v00 *= 1.f / (1.f + expf(-f0.x));
                v01 *= 1.f / (1.f + expf(-f0.y));
                v10 *= 1.f / (1.f + expf(-f1.x));
                v11 *= 1.f / (1.f + expf(-f1.y));
            }
            __half2 H0 = __floats2half2_rn(v00, v01);
            __half2 H1 = __floats2half2_rn(v10, v11);
            *(uint32_t*)(d.Ch + coff + (size_t)r * ldc + c) =
                *reinterpret_cast<uint32_t*>(&H0);
            *(uint32_t*)(d.Ch + coff + (size_t)(r + 8) * ldc + c) =
                *reinterpret_cast<uint32_t*>(&H1);
        }
    }
}

// ---------------- convert fp32 -> fp16 -------------------------------------
__global__ __launch_bounds__(256)
void cvt16_k(const float* __restrict__ src, __half* __restrict__ dst, size_t n)
{
    size_t i = ((size_t)blockIdx.x * blockDim.x + threadIdx.x) * 4;
    if (i >= n) return;
    float4 v = *(const float4*)(src + i);
    __half2 h0 = __floats2half2_rn(v.x, v.y);
    __half2 h1 = __floats2half2_rn(v.z, v.w);
    uint2 o = { *reinterpret_cast<uint32_t*>(&h0), *reinterpret_cast<uint32_t*>(&h1) };
    *(uint2*)((unsigned short*)dst + i) = o;
}

// ---------------- transpose + convert, 4 weights per launch ----------------
__global__ __launch_bounds__(256)
void tcvt4_k(const float* __restrict__ s0, const float* __restrict__ s1,
             const float* __restrict__ s2, const float* __restrict__ s3,
             __half* __restrict__ d0, __half* __restrict__ d1,
             __half* __restrict__ d2, __half* __restrict__ d3,
             int K, int Ncol, int zPerW)
{
    __shared__ float t[64][33];
    int w = blockIdx.z / zPerW;
    int z = blockIdx.z % zPerW;
    const float* src = (w == 0 ? s0 : w == 1 ? s1 : w == 2 ? s2 : s3)
                       + (size_t)z * K * Ncol;
    __half* dst = (w == 0 ? d0 : w == 1 ? d1 : w == 2 ? d2 : d3)
                  + (size_t)z * K * Ncol;
    int k0 = blockIdx.y * 64, n0 = blockIdx.x * 32;
#pragma unroll
    for (int r = 0; r < 8; r++)
        t[threadIdx.y + 8 * r][threadIdx.x] =
            src[(size_t)(k0 + threadIdx.y + 8 * r) * Ncol + n0 + threadIdx.x];
    __syncthreads();
#pragma unroll
    for (int r = 0; r < 4; r++) {
        int n = threadIdx.y + 8 * r;
        int kk = threadIdx.x;
        __half2 h = __floats2half2_rn(t[2 * kk][n], t[2 * kk + 1][n]);
        *(__half2*)(dst + (size_t)(n0 + n) * K + k0 + 2 * kk) = h;
    }
}

// ---------------- fused LN(4096)+softmax + per-(b,n) LN(256)+combine -------
// g and gv are fp16.
__global__ __launch_bounds__(256)
void final_k(const float* __restrict__ x, const __half* __restrict__ g,
             const float* __restrict__ gamma, const float* __restrict__ beta,
             const __half* __restrict__ gv, const float* __restrict__ vlng,
             const float* __restrict__ vlnb, float* __restrict__ out)
{
    __shared__ float s[FEAT];
    __shared__ float red[8];
    __shared__ float part[8][DDIM];
    const int b = blockIdx.x, t = threadIdx.x;
    const int lane = t & 31, wrp = t >> 5;
    const float* xb = x + (size_t)b * FEAT;
    const __half* gb = g + (size_t)b * FEAT;

    float lsum = 0.f;
    for (int i = t; i < FEAT; i += 256) {
        float v = xb[i] + __half2float(gb[i]);
        s[i] = v; lsum += v;
    }
#pragma unroll
    for (int o = 16; o; o >>= 1) lsum += __shfl_xor_sync(0xffffffff, lsum, o);
    if (lane == 0) red[wrp] = lsum;
    __syncthreads();
    float tot = 0.f;
#pragma unroll
    for (int i = 0; i < 8; i++) tot += red[i];
    float mean = tot * (1.f / FEAT);
    __syncthreads();

    float lvar = 0.f;
    for (int i = t; i < FEAT; i += 256) { float dd = s[i] - mean; lvar += dd * dd; }
#pragma unroll
    for (int o = 16; o; o >>= 1) lvar += __shfl_xor_sync(0xffffffff, lvar, o);
    if (lane == 0) red[wrp] = lvar;
    __syncthreads();
    float vtot = 0.f;
#pragma unroll
    for (int i = 0; i < 8; i++) vtot += red[i];
    float rstd = rsqrtf(vtot * (1.f / FEAT) + 1e-5f);

    for (int i = t; i < FEAT; i += 256)
        s[i] = (s[i] - mean) * rstd * gamma[i] + beta[i];
    __syncthreads();

    {
        float c[NVAR];
        float m = -1e30f;
#pragma unroll
        for (int n = 0; n < NVAR; n++) { c[n] = s[n * DDIM + t]; m = fmaxf(m, c[n]); }
        float sum = 0.f;
#pragma unroll
        for (int n = 0; n < NVAR; n++) { c[n] = expf(c[n] - m); sum += c[n]; }
        float inv = 1.f / sum;
#pragma unroll
        for (int n = 0; n < NVAR; n++) s[n * DDIM + t] = c[n] * inv;
    }
    __syncthreads();

    float accl[8];
#pragma unroll
    for (int j = 0; j < 8; j++) accl[j] = 0.f;

#pragma unroll
    for (int nn = 0; nn < 2; nn++) {
        const int n = wrp * 2 + nn;
        const size_t base = (size_t)b * FEAT + n * DDIM;
        float v[8];
        float sum = 0.f;
#pragma unroll
        for (int j = 0; j < 8; j++) {
            v[j] = x[base + lane + 32 * j] + __half2float(gv[base + lane + 32 * j]);
            sum += v[j];
        }
#pragma unroll
        for (int o = 16; o; o >>= 1) sum += __shfl_xor_sync(0xffffffff, sum, o);
        const float meanl = sum * (1.f / DDIM);
        float var = 0.f;
#pragma unroll
        for (int j = 0; j < 8; j++) { float dl = v[j] - meanl; var += dl * dl; }
#pragma unroll
        for (int o = 16; o; o >>= 1) var += __shfl_xor_sync(0xffffffff, var, o);
        const float rstdl = rsqrtf(var * (1.f / DDIM) + 1e-5f);
#pragma unroll
        for (int j = 0; j < 8; j++) {
            const int dcol = lane + 32 * j;
            float yv = (v[j] - meanl) * rstdl * vlng[n * DDIM + dcol]
                       + vlnb[n * DDIM + dcol];
            accl[j] += s[n * DDIM + dcol] * yv;
        }
    }
#pragma unroll
    for (int j = 0; j < 8; j++) part[wrp][lane + 32 * j] = accl[j];
    __syncthreads();
    float sm = 0.f;
#pragma unroll
    for (int k = 0; k < 8; k++) sm += part[k][t];
    out[(size_t)b * DDIM + t] = sm;
}

// ---------------- launch ----------------------------------------------------
extern "C" void kernel_launch(void* const* d_in, const int* in_sizes, int n_in,
                              void* d_out, int out_size)
{
    const float* x    = (const float*)d_in[0];
    const float* vW2  = (const float*)d_in[1];
    const float* vb2  = (const float*)d_in[2];
    const float* vW1  = (const float*)d_in[3];
    const float* vb1  = (const float*)d_in[4];
    const float* vW4  = (const float*)d_in[5];
    const float* vb4  = (const float*)d_in[6];
    const float* vW5  = (const float*)d_in[7];
    const float* vb5  = (const float*)d_in[8];
    const float* vlng = (const float*)d_in[9];
    const float* vlnb = (const float*)d_in[10];
    const float* cW2  = (const float*)d_in[11];
    const float* cb2  = (const float*)d_in[12];
    const float* cW1  = (const float*)d_in[13];
    const float* cb1  = (const float*)d_in[14];
    const float* cW4  = (const float*)d_in[15];
    const float* cb4  = (const float*)d_in[16];
    const float* cW5  = (const float*)d_in[17];
    const float* cb5  = (const float*)d_in[18];
    const float* clng = (const float*)d_in[19];
    const float* clnb = (const float*)d_in[20];
    float* out = (float*)d_out;

    __half *gc, *gv;
    cudaGetSymbolAddress((void**)&gc, g_gc);
    cudaGetSymbolAddress((void**)&gv, g_gv);
    __half *xh, *hh, *eh, *hv, *ev;
    cudaGetSymbolAddress((void**)&xh, g_xh);
    cudaGetSymbolAddress((void**)&hh, g_hh);
    cudaGetSymbolAddress((void**)&eh, g_eh);
    cudaGetSymbolAddress((void**)&hv, g_hv);
    cudaGetSymbolAddress((void**)&ev, g_ev);
    __half *cW2h, *cW1h, *cW4h, *cW5h;
    cudaGetSymbolAddress((void**)&cW2h, g_cW2h);
    cudaGetSymbolAddress((void**)&cW1h, g_cW1h);
    cudaGetSymbolAddress((void**)&cW4h, g_cW4h);
    cudaGetSymbolAddress((void**)&cW5h, g_cW5h);
    __half *vW2h, *vW1h, *vW4h, *vW5h;
    cudaGetSymbolAddress((void**)&vW2h, g_vW2h);
    cudaGetSymbolAddress((void**)&vW1h, g_vW1h);
    cudaGetSymbolAddress((void**)&vW4h, g_vW4h);
    cudaGetSymbolAddress((void**)&vW5h, g_vW5h);

    cudaFuncSetAttribute(mgemm_k<1>, cudaFuncAttributeMaxDynamicSharedMemorySize, GEMM_SMEM);
    cudaFuncSetAttribute(mgemm_k<0>, cudaFuncAttributeMaxDynamicSharedMemorySize, GEMM_SMEM);
    cudaFuncSetAttribute(mgemm_k<2>, cudaFuncAttributeMaxDynamicSharedMemorySize, GEMM_SMEM);

    const size_t NE = NELEM;

    // ---- conversions ----
    cvt16_k<<<(unsigned)(NE / 1024), 256>>>(x, xh, NE);
    {
        dim3 b(32, 8);
        dim3 gcg(FEAT / 32, FEAT / 64, 4);
        tcvt4_k<<<gcg, b>>>(cW2, cW1, cW4, cW5, cW2h, cW1h, cW4h, cW5h,
                            FEAT, FEAT, 1);
        dim3 gvg(DDIM / 32, DDIM / 64, 4 * NVAR);
        tcvt4_k<<<gvg, b>>>(vW2, vW1, vW4, vW5, vW2h, vW1h, vW4h, vW5h,
                            DDIM, DDIM, NVAR);
    }

    // ---- descriptor templates ----
    const int ccTiles = (FEAT / BN) * (BATCH / BM);   // 32*32 = 1024
    const int vTilesZ = (DDIM / BN) * (BATCH / BM);   // 2*32  = 64
    const int vTiles  = vTilesZ * NVAR;               // 1024
    const unsigned totalTiles = ccTiles + vTiles;     // 2048

    auto mkC = [&](const __half* A, const __half* B, const float* bias,
                   const __half* auxh, __half* ch) {
        GDesc d;
        d.A = A; d.B = B; d.bias = bias; d.AuxH = auxh; d.Ch = ch;
        d.K = FEAT; d.lda = FEAT; d.ldb = FEAT; d.ldc = FEAT;
        d.sAn = 0; d.sBn = 0; d.sBiasN = 0; d.sCn = 0;
        d.ntN = FEAT / BN; d.tilesPerZ = ccTiles;
        return d;
    };
    auto mkV = [&](const __half* A, const __half* B, const float* bias,
                   const __half* auxh, __half* ch) {
        GDesc d;
        d.A = A; d.B = B; d.bias = bias; d.AuxH = auxh; d.Ch = ch;
        d.K = DDIM; d.lda = FEAT; d.ldb = DDIM; d.ldc = FEAT;
        d.sAn = DDIM; d.sBn = (long)DDIM * DDIM; d.sBiasN = DDIM; d.sCn = DDIM;
        d.ntN = DDIM / BN; d.tilesPerZ = vTilesZ;
        return d;
    };

    // ---- merged GEMM launches ----
    // L1: h = elu(x@W2+b2)  -> hh / hv
    mgemm_k<1><<<totalTiles, 256, GEMM_SMEM>>>(
        mkC(xh, cW2h, cb2, nullptr, hh),
        mkV(xh, vW2h, vb2, nullptr, hv), ccTiles);
    // L2: e1 = h@W1+b1      -> eh / ev
    mgemm_k<0><<<totalTiles, 256, GEMM_SMEM>>>(
        mkC(hh, cW1h, cb1, nullptr, eh),
        mkV(hv, vW1h, vb1, nullptr, ev), ccTiles);
    // L3: t4 = e1@W4+b4     -> hh / hv
    mgemm_k<0><<<totalTiles, 256, GEMM_SMEM>>>(
        mkC(eh, cW4h, cb4, nullptr, hh),
        mkV(ev, vW4h, vb4, nullptr, hv), ccTiles);
    // L4: g = sigmoid(t4) * (e1@W5+b5)  -> gc / gv (fp16)
    mgemm_k<2><<<totalTiles, 256, GEMM_SMEM>>>(
        mkC(eh, cW5h, cb5, hh, gc),
        mkV(ev, vW5h, vb5, hv, gv), ccTiles);

    // ---- fused LN+softmax+combine ----
    final_k<<<BATCH, 256>>>(x, gc, clng, clnb, gv, vlng, vlnb, out);
}